// round 8
// baseline (speedup 1.0000x reference)
#include <cuda_runtime.h>
#include <mma.h>
#include <cstdint>

using namespace nvcuda;

#define Ecfg 1024
#define Hh   16
#define HKV  4
#define Dd   64

#define BM  128
#define BN  128
#define LDA 40
#define LDK 72

// ---------------- scratch (device globals) ----------------
__device__ float g_qraw[2 * 2048 * 1024];
__device__ float g_kraw[2 * 2048 * 256];
__device__ float g_vraw[2 * 2048 * 256];
__device__ float g_qt  [2 * 16 * 2048 * 64];
__device__ float g_kt  [2 * 4  * 2048 * 64];
__device__ float g_vt  [2 * 4  * 2048 * 64];
__device__ float g_attn[2 * 2048 * 1024];
__device__ float g_xtf [2 * 2048 * 1024];
__device__ float g_wqt [1024 * 1024];
__device__ float g_wkt [256 * 1024];
__device__ float g_wvt [256 * 1024];
__device__ float g_wpt [1024 * 1024];

// ---------------- cp.async helpers ----------------
__device__ __forceinline__ void cp16(float* smem_dst, const float* gsrc) {
    uint32_t s = (uint32_t)__cvta_generic_to_shared(smem_dst);
    asm volatile("cp.async.cg.shared.global [%0], [%1], 16;\n" :: "r"(s), "l"(gsrc));
}
#define CP_COMMIT() asm volatile("cp.async.commit_group;\n" ::: "memory")
#define CP_WAIT1()  asm volatile("cp.async.wait_group 1;\n" ::: "memory")
#define CP_WAIT0()  asm volatile("cp.async.wait_group 0;\n" ::: "memory")

// ---------------- branch-light fast exp2: p = 2^x, x in [-25, 0.1] ----------------
// magic-number round (no F2I), deg-5 poly on f in [-0.5, 0.5], exponent splice.
// rel err <= ~2.4e-6 — negligible vs tf32 score noise. All fixed-lat fma/alu ops.
__device__ __forceinline__ float fast_exp2(float x) {
    float t = x + 12582912.0f;                     // 1.5 * 2^23, RN to integer
    int   ei = __float_as_int(t) - 0x4B400000;     // n as signed int
    float f = x - (t - 12582912.0f);               // f in [-0.5, 0.5]
    float e = fmaf(f, 0.0013333558f, 0.0096181291f);
    e = fmaf(f, e, 0.0555041087f);
    e = fmaf(f, e, 0.2402265070f);
    e = fmaf(f, e, 0.6931471806f);
    e = fmaf(f, e, 1.0f);
    return __int_as_float(__float_as_int(e) + (ei << 23));
}
#define LOG2E_F  1.4426950408889634f
#define NBIAS_F  (-11.541560327111707f)   /* -8 * log2e */

// ---------------- fused tf32 pre-round of x + all weights (1 launch) ----------------
#define N4_WQ 262144
#define N4_WK 65536
#define N4_WV 65536
#define N4_WP 262144
__global__ void cvt_all(const float* __restrict__ x,  const float* __restrict__ wq,
                        const float* __restrict__ wk, const float* __restrict__ wv,
                        const float* __restrict__ wp,
                        float* __restrict__ xo, float* __restrict__ wqo,
                        float* __restrict__ wko, float* __restrict__ wvo,
                        float* __restrict__ wpo, int n4x) {
    int i = blockIdx.x * blockDim.x + threadIdx.x;
    const float4* s; float4* d; int j;
    if (i < n4x) { s = (const float4*)x; d = (float4*)xo; j = i; }
    else {
        i -= n4x;
        if (i < N4_WQ)                          { s = (const float4*)wq; d = (float4*)wqo; j = i; }
        else if (i < N4_WQ + N4_WK)             { s = (const float4*)wk; d = (float4*)wko; j = i - N4_WQ; }
        else if (i < N4_WQ + N4_WK + N4_WV)     { s = (const float4*)wv; d = (float4*)wvo; j = i - N4_WQ - N4_WK; }
        else if (i < N4_WQ + N4_WK + N4_WV + N4_WP) { s = (const float4*)wp; d = (float4*)wpo; j = i - N4_WQ - N4_WK - N4_WV; }
        else return;
    }
    float4 v = s[j];
    v.x = wmma::__float_to_tf32(v.x); v.y = wmma::__float_to_tf32(v.y);
    v.z = wmma::__float_to_tf32(v.z); v.w = wmma::__float_to_tf32(v.w);
    d[j] = v;
}

// ================= TF32 GEMM, cp.async 2-stage: C[M,N] = A @ W^T =================
// BM=BN=128, BK=32, 256 thr = 8 warps (2M x 4N), warp tile 64x32 (acc 4x2).
__device__ __forceinline__ void gemm_core(
    const float* __restrict__ A, const float* __restrict__ W,
    float* __restrict__ C, int N, int K, int m0, int n0) {
    extern __shared__ float sm[];
    float* As = sm;                   // 2 * 128 * LDA
    float* Ws = sm + 2 * BM * LDA;    // 2 * 128 * LDA
    const int tid = threadIdx.x;
    const int warp = tid >> 5;
    const int wm = warp >> 2;   // 0..1 : 64-row strip
    const int wn = warp & 3;    // 0..3 : 32-col strip

    wmma::fragment<wmma::accumulator, 16, 16, 8, float> acc[4][2];
#pragma unroll
    for (int i = 0; i < 4; i++)
#pragma unroll
        for (int j = 0; j < 2; j++) wmma::fill_fragment(acc[i][j], 0.f);

    const float* Ab = A + (size_t)m0 * K;
    const float* Wb = W + (size_t)n0 * K;

#define LOAD_SLAB(it, buf)                                                      \
    {                                                                           \
        const int k0 = (it) << 5;                                               \
        float* ad = As + (buf) * BM * LDA;                                      \
        float* wd = Ws + (buf) * BN * LDA;                                      \
        _Pragma("unroll")                                                       \
        for (int i = 0; i < 4; i++) {                                           \
            int ch = tid + i * 256;                                             \
            int r = ch >> 3, c4 = (ch & 7) << 2;                                \
            cp16(ad + r * LDA + c4, Ab + (size_t)r * K + k0 + c4);              \
            cp16(wd + r * LDA + c4, Wb + (size_t)r * K + k0 + c4);              \
        }                                                                       \
    }

    const int nIter = K >> 5;
    LOAD_SLAB(0, 0); CP_COMMIT();
    for (int it = 0; it < nIter; ++it) {
        const int buf = it & 1;
        if (it + 1 < nIter) { LOAD_SLAB(it + 1, buf ^ 1); CP_COMMIT(); CP_WAIT1(); }
        else CP_WAIT0();
        __syncthreads();
        const float* as = As + buf * BM * LDA;
        const float* ws = Ws + buf * BN * LDA;
#pragma unroll
        for (int kk = 0; kk < 32; kk += 8) {
            wmma::fragment<wmma::matrix_a, 16, 16, 8, wmma::precision::tf32, wmma::row_major> a[4];
            wmma::fragment<wmma::matrix_b, 16, 16, 8, wmma::precision::tf32, wmma::col_major> b[2];
#pragma unroll
            for (int i = 0; i < 4; i++)
                wmma::load_matrix_sync(a[i], &as[(wm * 64 + i * 16) * LDA + kk], LDA);
#pragma unroll
            for (int j = 0; j < 2; j++)
                wmma::load_matrix_sync(b[j], &ws[(wn * 32 + j * 16) * LDA + kk], LDA);
#pragma unroll
            for (int i = 0; i < 4; i++)
#pragma unroll
                for (int j = 0; j < 2; j++)
                    wmma::mma_sync(acc[i][j], a[i], b[j], acc[i][j]);
        }
        __syncthreads();
    }
#undef LOAD_SLAB
#pragma unroll
    for (int i = 0; i < 4; i++)
#pragma unroll
        for (int j = 0; j < 2; j++)
            wmma::store_matrix_sync(&C[(size_t)(m0 + wm * 64 + i * 16) * N + n0 + wn * 32 + j * 16],
                                    acc[i][j], N, wmma::mem_row_major);
}

__global__ __launch_bounds__(256, 2) void gemm_proj(
    const float* __restrict__ A, const float* __restrict__ W, float* __restrict__ C, int K) {
    gemm_core(A, W, C, Ecfg, K, blockIdx.y * BM, blockIdx.x * BN);
}

// fused QKV: 12 n-tiles = 8 (Q, N=1024) + 2 (K, N=256) + 2 (V, N=256)
__global__ __launch_bounds__(256, 2) void gemm_qkv(
    const float* __restrict__ x,
    const float* __restrict__ Wq, const float* __restrict__ Wk, const float* __restrict__ Wv,
    float* __restrict__ Cq, float* __restrict__ Ck, float* __restrict__ Cv, int K) {
    const int ng = blockIdx.x * BN;
    const float* W; float* C; int N, n0;
    if (ng < 1024)      { W = Wq; C = Cq; N = 1024; n0 = ng; }
    else if (ng < 1280) { W = Wk; C = Ck; N = 256;  n0 = ng - 1024; }
    else                { W = Wv; C = Cv; N = 256;  n0 = ng - 1280; }
    gemm_core(x, W, C, N, K, blockIdx.y * BM, n0);
}

// ---------------- rope + rmsnorm for Q (writes tf32-rounded) ----------------
__global__ void rope_rms_kernel(const float* __restrict__ raw,
                                const float* __restrict__ cosb,
                                const float* __restrict__ sinb,
                                float* __restrict__ dst, int T) {
    const int warp = threadIdx.x >> 5, lane = threadIdx.x & 31;
    const int t = blockIdx.x * 8 + warp;
    const int h = blockIdx.y, b = blockIdx.z;
    const int NH = gridDim.y;
    const float* src = raw + (((size_t)b * T + t) * NH + h) * 64;
    float x1 = src[lane], x2 = src[32 + lane];
    float c = cosb[(size_t)t * 32 + lane];
    float s = sinb[(size_t)t * 32 + lane];
    float r1 = x1 * c + x2 * s;
    float r2 = x2 * c - x1 * s;
    float ss = r1 * r1 + r2 * r2;
#pragma unroll
    for (int o = 16; o; o >>= 1) ss += __shfl_xor_sync(0xffffffffu, ss, o);
    float inv = rsqrtf(ss * (1.f / 64.f) + 1.1920929e-07f);
    float* d = dst + (((size_t)b * NH + h) * T + t) * 64;
    d[lane] = wmma::__float_to_tf32(r1 * inv);
    d[32 + lane] = wmma::__float_to_tf32(r2 * inv);
}

// ---------------- fused K rope+rms AND V gate (writes tf32-rounded) ----------------
__global__ void kv_post_kernel(const float* __restrict__ kraw,
                               const float* __restrict__ vraw,
                               const float* __restrict__ x,
                               const float* __restrict__ ve,
                               const float* __restrict__ cosb,
                               const float* __restrict__ sinb,
                               const float* __restrict__ Wgate,
                               float* __restrict__ k_t,
                               float* __restrict__ v_t, int T) {
    const int warp = threadIdx.x >> 5, lane = threadIdx.x & 31;
    const int t = blockIdx.x * 8 + warp;
    const int h = blockIdx.y, b = blockIdx.z;
    const size_t tok = (size_t)b * T + t;
    {
        const float* src = kraw + (tok * HKV + h) * 64;
        float x1 = src[lane], x2 = src[32 + lane];
        float c = cosb[(size_t)t * 32 + lane];
        float s = sinb[(size_t)t * 32 + lane];
        float r1 = x1 * c + x2 * s;
        float r2 = x2 * c - x1 * s;
        float ss = r1 * r1 + r2 * r2;
#pragma unroll
        for (int o = 16; o; o >>= 1) ss += __shfl_xor_sync(0xffffffffu, ss, o);
        float inv = rsqrtf(ss * (1.f / 64.f) + 1.1920929e-07f);
        float* d = k_t + (((size_t)b * HKV + h) * T + t) * 64;
        d[lane] = wmma::__float_to_tf32(r1 * inv);
        d[32 + lane] = wmma::__float_to_tf32(r2 * inv);
    }
    {
        float g = x[tok * Ecfg + lane] * Wgate[h * 32 + lane];
#pragma unroll
        for (int o = 16; o; o >>= 1) g += __shfl_xor_sync(0xffffffffu, g, o);
        float gate = 2.f / (1.f + __expf(-g));
        const float* vs = vraw + (tok * HKV + h) * 64;
        const float* ves = ve + (tok * HKV + h) * 64;
        float* d = v_t + (((size_t)b * HKV + h) * T + t) * 64;
        d[lane] = wmma::__float_to_tf32(vs[lane] + gate * ves[lane]);
        d[32 + lane] = wmma::__float_to_tf32(vs[32 + lane] + gate * ves[32 + lane]);
    }
}

// ================ sliding-window flash attention: 32-row warps ================
// 128 thr = 4 warps; warp w owns query rows [32w, 32w+32) of a 128-row Q tile.
// K/V double-buffered via cp.async. Fixed-max softmax: p = exp2((s-8)*log2e)
// via MUFU-free fast_exp2 (the exp count — ~50M — was the kernel's roofline).
__global__ __launch_bounds__(128, 2) void attn_tc(
    const float* __restrict__ q, const float* __restrict__ k,
    const float* __restrict__ v, float* __restrict__ out,
    const int* __restrict__ wptr, int T) {
    extern __shared__ float sm[];
    float* Ks = sm;                    // 2 * 64 * LDK
    float* Vs = sm + 2 * 64 * LDK;     // 2 * 64 * LDK
    float* Ss = sm + 4 * 64 * LDK;     // 128 * LDK

    const int qtile = blockIdx.x, h = blockIdx.y, b = blockIdx.z;
    const int W = wptr[0];
    const int tid = threadIdx.x;
    const int warp = tid >> 5, lane = tid & 31;
    const int qbase = qtile * 128;
    const int half = lane & 1;

    // persistent Q fragments: 2 strips x 8 k-frags (tf32 pre-rounded; *0.125 exact)
    wmma::fragment<wmma::matrix_a, 16, 16, 8, wmma::precision::tf32, wmma::row_major> qf[2][8];
#pragma unroll
    for (int i = 0; i < 2; i++) {
        const float* qptr = q + ((size_t)(b * Hh + h) * T + qbase + warp * 32 + i * 16) * Dd;
#pragma unroll
        for (int kk = 0; kk < 8; kk++) {
            wmma::load_matrix_sync(qf[i][kk], qptr + kk * 8, Dd);
#pragma unroll
            for (int e = 0; e < qf[i][kk].num_elements; e++)
                qf[i][kk].x[e] *= 0.125f;
        }
    }
    wmma::fragment<wmma::accumulator, 16, 16, 8, float> oa[2][4];
#pragma unroll
    for (int i = 0; i < 2; i++)
#pragma unroll
        for (int j = 0; j < 4; j++) wmma::fill_fragment(oa[i][j], 0.f);

    const int hkv = h >> 2;
    const float* kb = k + (size_t)(b * HKV + hkv) * T * Dd;
    const float* vb = v + (size_t)(b * HKV + hkv) * T * Dd;
    int kmin = qbase - W; if (kmin < 0) kmin = 0;
    const int t0 = kmin >> 6;
    const int ktend = 2 * qtile + 1;   // last 64-key tile overlapping this Q tile

#define LOAD_KV(kt, buf)                                                        \
    {                                                                           \
        const float* kp = kb + (size_t)(kt) * 64 * Dd;                          \
        const float* vp = vb + (size_t)(kt) * 64 * Dd;                          \
        float* kd = Ks + (buf) * 64 * LDK;                                      \
        float* vd = Vs + (buf) * 64 * LDK;                                      \
        _Pragma("unroll")                                                       \
        for (int i = 0; i < 8; i++) {                                           \
            int ch = tid + i * 128;                                             \
            int r = ch >> 4, c4 = (ch & 15) << 2;                               \
            cp16(kd + r * LDK + c4, kp + r * 64 + c4);                          \
            cp16(vd + r * LDK + c4, vp + r * 64 + c4);                          \
        }                                                                       \
    }

    LOAD_KV(t0, 0); CP_COMMIT();
    float l_run[2] = {0.f, 0.f};

    for (int kt = t0; kt <= ktend; ++kt) {
        const int buf = (kt - t0) & 1;
        if (kt < ktend) { LOAD_KV(kt + 1, buf ^ 1); CP_COMMIT(); CP_WAIT1(); }
        else CP_WAIT0();
        __syncthreads();
        const float* ks = Ks + buf * 64 * LDK;
        const float* vs = Vs + buf * 64 * LDK;

        // S = Q @ K^T : 32x64 per warp, K-frag shared across the 2 row strips
        {
            wmma::fragment<wmma::accumulator, 16, 16, 8, float> sa[2][4];
#pragma unroll
            for (int i = 0; i < 2; i++)
#pragma unroll
                for (int j = 0; j < 4; j++) wmma::fill_fragment(sa[i][j], 0.f);
#pragma unroll
            for (int kk = 0; kk < 8; kk++) {
#pragma unroll
                for (int j = 0; j < 4; j++) {
                    wmma::fragment<wmma::matrix_b, 16, 16, 8, wmma::precision::tf32, wmma::col_major> bf;
                    wmma::load_matrix_sync(bf, &ks[(j * 16) * LDK + kk * 8], LDK);
                    wmma::mma_sync(sa[0][j], qf[0][kk], bf, sa[0][j]);
                    wmma::mma_sync(sa[1][j], qf[1][kk], bf, sa[1][j]);
                }
            }
#pragma unroll
            for (int i = 0; i < 2; i++)
#pragma unroll
                for (int j = 0; j < 4; j++)
                    wmma::store_matrix_sync(&Ss[(warp * 32 + i * 16) * LDK + j * 16],
                                            sa[i][j], LDK, wmma::mem_row_major);
        }
        __syncwarp();

        // fixed-max softmax via fast_exp2 (no MUFU); 4-way split l accumulator
        {
#pragma unroll
            for (int p = 0; p < 2; p++) {
                const int sRow = warp * 32 + p * 16 + (lane >> 1);
                const int qrow = qbase + sRow;
                float* srow = &Ss[sRow * LDK + half * 32];
                const int colbase = (kt << 6) + (half << 5);
                const int cmax = qrow - colbase;          // c <= cmax
                const int cmin = qrow - W - colbase;      // c >= cmin
                float lacc[4] = {0.f, 0.f, 0.f, 0.f};
#pragma unroll
                for (int c = 0; c < 32; c++) {
                    float pv = 0.f;
                    if (c <= cmax && c >= cmin) {
                        float xx = fmaf(srow[c], LOG2E_F, NBIAS_F);
                        pv = fast_exp2(xx);
                        lacc[c & 3] += pv;
                    }
                    srow[c] = wmma::__float_to_tf32(pv);
                }
                l_run[p] += (lacc[0] + lacc[1]) + (lacc[2] + lacc[3]);
            }
        }
        __syncwarp();

        // O += P @ V : V-frag shared across the 2 row strips
#pragma unroll
        for (int kk = 0; kk < 8; kk++) {
            wmma::fragment<wmma::matrix_a, 16, 16, 8, wmma::precision::tf32, wmma::row_major> pf[2];
#pragma unroll
            for (int i = 0; i < 2; i++)
                wmma::load_matrix_sync(pf[i], &Ss[(warp * 32 + i * 16) * LDK + kk * 8], LDK);
#pragma unroll
            for (int j = 0; j < 4; j++) {
                wmma::fragment<wmma::matrix_b, 16, 16, 8, wmma::precision::tf32, wmma::row_major> bf;
                wmma::load_matrix_sync(bf, &vs[(kk * 8) * LDK + j * 16], LDK);
                wmma::mma_sync(oa[0][j], pf[0], bf, oa[0][j]);
                wmma::mma_sync(oa[1][j], pf[1], bf, oa[1][j]);
            }
        }
        __syncthreads();
    }
#undef LOAD_KV

    // epilogue: stage O, normalize per row, write tf32-rounded [B,T,H,D]
#pragma unroll
    for (int i = 0; i < 2; i++)
#pragma unroll
        for (int j = 0; j < 4; j++)
            wmma::store_matrix_sync(&Ss[(warp * 32 + i * 16) * LDK + j * 16],
                                    oa[i][j], LDK, wmma::mem_row_major);
    __syncwarp();
#pragma unroll
    for (int p = 0; p < 2; p++) {
        const int sRow = warp * 32 + p * 16 + (lane >> 1);
        const int qrow = qbase + sRow;
        float l_tot = l_run[p] + __shfl_xor_sync(0xffffffffu, l_run[p], 1);
        float inv = 1.f / l_tot;
        float* op = out + ((size_t)(b * T + qrow) * Hh + h) * Dd + half * 32;
        const float* orow = &Ss[sRow * LDK + half * 32];
#pragma unroll
        for (int c = 0; c < 32; c += 4) {
            float4 o = make_float4(wmma::__float_to_tf32(orow[c] * inv),
                                   wmma::__float_to_tf32(orow[c + 1] * inv),
                                   wmma::__float_to_tf32(orow[c + 2] * inv),
                                   wmma::__float_to_tf32(orow[c + 3] * inv));
            *reinterpret_cast<float4*>(&op[c]) = o;
        }
    }
}

// ---------------- launch ----------------
extern "C" void kernel_launch(void* const* d_in, const int* in_sizes, int n_in,
                              void* d_out, int out_size) {
    const float* x     = (const float*)d_in[0];
    const float* ve    = (const float*)d_in[1];
    const float* cosb  = (const float*)d_in[2];
    const float* sinb  = (const float*)d_in[3];
    const float* Wq    = (const float*)d_in[4];
    const float* Wk    = (const float*)d_in[5];
    const float* Wv    = (const float*)d_in[6];
    const float* Wproj = (const float*)d_in[7];
    const float* Wgate = (const float*)d_in[8];
    const int*   wsz   = (const int*)d_in[9];

    int T = in_sizes[2] / 32;
    int B = in_sizes[0] / (T * Ecfg);
    int M = B * T;

    float *qraw, *kraw, *vraw, *qt, *kt, *vt, *attn;
    float *xtf, *wqt, *wkt, *wvt, *wpt;
    cudaGetSymbolAddress((void**)&qraw, g_qraw);
    cudaGetSymbolAddress((void**)&kraw, g_kraw);
    cudaGetSymbolAddress((void**)&vraw, g_vraw);
    cudaGetSymbolAddress((void**)&qt,   g_qt);
    cudaGetSymbolAddress((void**)&kt,   g_kt);
    cudaGetSymbolAddress((void**)&vt,   g_vt);
    cudaGetSymbolAddress((void**)&attn, g_attn);
    cudaGetSymbolAddress((void**)&xtf,  g_xtf);
    cudaGetSymbolAddress((void**)&wqt,  g_wqt);
    cudaGetSymbolAddress((void**)&wkt,  g_wkt);
    cudaGetSymbolAddress((void**)&wvt,  g_wvt);
    cudaGetSymbolAddress((void**)&wpt,  g_wpt);

    const int gemm_smem = 2 * (BM + BN) * LDA * 4;          // 81920
    const int attn_smem = (4 * 64 * LDK + 128 * LDK) * 4;   // 110592
    cudaFuncSetAttribute(gemm_qkv,  cudaFuncAttributeMaxDynamicSharedMemorySize, gemm_smem);
    cudaFuncSetAttribute(gemm_proj, cudaFuncAttributeMaxDynamicSharedMemorySize, gemm_smem);
    cudaFuncSetAttribute(attn_tc,   cudaFuncAttributeMaxDynamicSharedMemorySize, attn_smem);

    // single fused tf32 pre-round: x + all 4 weight matrices
    {
        int n4x = M * Ecfg / 4;
        int total = n4x + N4_WQ + N4_WK + N4_WV + N4_WP;
        cvt_all<<<(total + 255) / 256, 256>>>(x, Wq, Wk, Wv, Wproj,
                                              xtf, wqt, wkt, wvt, wpt, n4x);
    }

    gemm_qkv<<<dim3(1536 / BN, M / BM), 256, gemm_smem>>>(xtf, wqt, wkt, wvt, qraw, kraw, vraw, Ecfg);

    rope_rms_kernel<<<dim3(T / 8, Hh, B), 256>>>(qraw, cosb, sinb, qt, T);
    kv_post_kernel <<<dim3(T / 8, HKV, B), 256>>>(kraw, vraw, x, ve, cosb, sinb, Wgate, kt, vt, T);

    attn_tc<<<dim3(T / 128, Hh, B), 128, attn_smem>>>(qt, kt, vt, attn, wsz, T);

    gemm_proj<<<dim3(Ecfg / BN, M / BM), 256, gemm_smem>>>(attn, wpt, (float*)d_out, Ecfg);
}

// round 9
// speedup vs baseline: 2.3056x; 2.3056x over previous
#include <cuda_runtime.h>
#include <cuda_fp16.h>
#include <mma.h>
#include <cstdint>

using namespace nvcuda;

#define Ecfg 1024
#define Hh   16
#define HKV  4
#define Dd   64

#define BM  128
#define BN  128
#define LDA 40    // halves; 80B row stride -> ldmatrix conflict-free (stride 20 words)
#define LDK 72    // halves; 144B row stride (36 words) -> 8-row groups distinct banks
#define LDS_F 72  // floats, for S/O staging

// ---------------- scratch (device globals) ----------------
__device__ float  g_qraw[2 * 2048 * 1024];
__device__ float  g_kraw[2 * 2048 * 256];
__device__ float  g_vraw[2 * 2048 * 256];
__device__ __half g_qt [2 * 16 * 2048 * 64];
__device__ __half g_kt [2 * 4  * 2048 * 64];
__device__ __half g_vt [2 * 4  * 2048 * 64];
__device__ __half g_y  [2 * 2048 * 1024];
__device__ __half g_xh [2 * 2048 * 1024];
__device__ __half g_wqh[1024 * 1024];
__device__ __half g_wkh[256 * 1024];
__device__ __half g_wvh[256 * 1024];
__device__ __half g_wph[1024 * 1024];

// ---------------- cp.async helpers ----------------
__device__ __forceinline__ void cp16(void* smem_dst, const void* gsrc) {
    uint32_t s = (uint32_t)__cvta_generic_to_shared(smem_dst);
    asm volatile("cp.async.cg.shared.global [%0], [%1], 16;\n" :: "r"(s), "l"(gsrc));
}
#define CP_COMMIT() asm volatile("cp.async.commit_group;\n" ::: "memory")
#define CP_WAIT1()  asm volatile("cp.async.wait_group 1;\n" ::: "memory")
#define CP_WAIT0()  asm volatile("cp.async.wait_group 0;\n" ::: "memory")

// ---------------- fast exp2 (no MUFU): p = 2^x, x in [-25, 0.2] ----------------
__device__ __forceinline__ float fast_exp2(float x) {
    float t = x + 12582912.0f;
    int   ei = __float_as_int(t) - 0x4B400000;
    float f = x - (t - 12582912.0f);
    float e = fmaf(f, 0.0013333558f, 0.0096181291f);
    e = fmaf(f, e, 0.0555041087f);
    e = fmaf(f, e, 0.2402265070f);
    e = fmaf(f, e, 0.6931471806f);
    e = fmaf(f, e, 1.0f);
    return __int_as_float(__float_as_int(e) + (ei << 23));
}
#define LOG2E_F  1.4426950408889634f
#define NBIAS_F  (-11.541560327111707f)   /* -8 * log2e */

// ---------------- fused fp16 convert of x + all weights (1 launch) ----------------
#define N4_WQ 262144
#define N4_WK 65536
#define N4_WV 65536
#define N4_WP 262144
__global__ void cvt_all(const float* __restrict__ x,  const float* __restrict__ wq,
                        const float* __restrict__ wk, const float* __restrict__ wv,
                        const float* __restrict__ wp,
                        __half* __restrict__ xo, __half* __restrict__ wqo,
                        __half* __restrict__ wko, __half* __restrict__ wvo,
                        __half* __restrict__ wpo, int n4x) {
    int i = blockIdx.x * blockDim.x + threadIdx.x;
    const float4* s; __half* d; int j;
    if (i < n4x) { s = (const float4*)x; d = xo; j = i; }
    else {
        i -= n4x;
        if (i < N4_WQ)                          { s = (const float4*)wq; d = wqo; j = i; }
        else if (i < N4_WQ + N4_WK)             { s = (const float4*)wk; d = wko; j = i - N4_WQ; }
        else if (i < N4_WQ + N4_WK + N4_WV)     { s = (const float4*)wv; d = wvo; j = i - N4_WQ - N4_WK; }
        else if (i < N4_WQ + N4_WK + N4_WV + N4_WP) { s = (const float4*)wp; d = wpo; j = i - N4_WQ - N4_WK - N4_WV; }
        else return;
    }
    float4 v = s[j];
    __half2 h0 = __floats2half2_rn(v.x, v.y);
    __half2 h1 = __floats2half2_rn(v.z, v.w);
    *reinterpret_cast<__half2*>(&d[j * 4])     = h0;
    *reinterpret_cast<__half2*>(&d[j * 4 + 2]) = h1;
}

// ================= FP16 GEMM, cp.async 2-stage: C[M,N] = A @ W^T =================
// BM=BN=128, BK=32, 256 thr = 8 warps (2M x 4N), warp tile 64x32, m16n16k16.
__device__ __forceinline__ void gemm_core(
    const __half* __restrict__ A, const __half* __restrict__ W,
    float* __restrict__ C, int N, int K, int m0, int n0) {
    extern __shared__ __half smh[];
    __half* As = smh;                   // 2 * 128 * LDA
    __half* Ws = smh + 2 * BM * LDA;    // 2 * 128 * LDA
    const int tid = threadIdx.x;
    const int warp = tid >> 5;
    const int wm = warp >> 2;   // 0..1 : 64-row strip
    const int wn = warp & 3;    // 0..3 : 32-col strip

    wmma::fragment<wmma::accumulator, 16, 16, 16, float> acc[4][2];
#pragma unroll
    for (int i = 0; i < 4; i++)
#pragma unroll
        for (int j = 0; j < 2; j++) wmma::fill_fragment(acc[i][j], 0.f);

    const __half* Ab = A + (size_t)m0 * K;
    const __half* Wb = W + (size_t)n0 * K;

#define LOAD_SLAB(it, buf)                                                      \
    {                                                                           \
        const int k0 = (it) << 5;                                               \
        __half* ad = As + (buf) * BM * LDA;                                     \
        __half* wd = Ws + (buf) * BN * LDA;                                     \
        _Pragma("unroll")                                                       \
        for (int i = 0; i < 2; i++) {                                           \
            int ch = tid + i * 256;          /* 0..511 */                       \
            int r = ch >> 2, c8 = (ch & 3) << 3;                                \
            cp16(ad + r * LDA + c8, Ab + (size_t)r * K + k0 + c8);              \
            cp16(wd + r * LDA + c8, Wb + (size_t)r * K + k0 + c8);              \
        }                                                                       \
    }

    const int nIter = K >> 5;
    LOAD_SLAB(0, 0); CP_COMMIT();
    for (int it = 0; it < nIter; ++it) {
        const int buf = it & 1;
        if (it + 1 < nIter) { LOAD_SLAB(it + 1, buf ^ 1); CP_COMMIT(); CP_WAIT1(); }
        else CP_WAIT0();
        __syncthreads();
        const __half* as = As + buf * BM * LDA;
        const __half* ws = Ws + buf * BN * LDA;
#pragma unroll
        for (int kk = 0; kk < 32; kk += 16) {
            wmma::fragment<wmma::matrix_a, 16, 16, 16, __half, wmma::row_major> a[4];
            wmma::fragment<wmma::matrix_b, 16, 16, 16, __half, wmma::col_major> b[2];
#pragma unroll
            for (int i = 0; i < 4; i++)
                wmma::load_matrix_sync(a[i], &as[(wm * 64 + i * 16) * LDA + kk], LDA);
#pragma unroll
            for (int j = 0; j < 2; j++)
                wmma::load_matrix_sync(b[j], &ws[(wn * 32 + j * 16) * LDA + kk], LDA);
#pragma unroll
            for (int i = 0; i < 4; i++)
#pragma unroll
                for (int j = 0; j < 2; j++)
                    wmma::mma_sync(acc[i][j], a[i], b[j], acc[i][j]);
        }
        __syncthreads();
    }
#undef LOAD_SLAB
#pragma unroll
    for (int i = 0; i < 4; i++)
#pragma unroll
        for (int j = 0; j < 2; j++)
            wmma::store_matrix_sync(&C[(size_t)(m0 + wm * 64 + i * 16) * N + n0 + wn * 32 + j * 16],
                                    acc[i][j], N, wmma::mem_row_major);
}

__global__ __launch_bounds__(256) void gemm_proj(
    const __half* __restrict__ A, const __half* __restrict__ W, float* __restrict__ C, int K) {
    gemm_core(A, W, C, Ecfg, K, blockIdx.y * BM, blockIdx.x * BN);
}

// fused QKV: 12 n-tiles = 8 (Q, N=1024) + 2 (K, N=256) + 2 (V, N=256)
__global__ __launch_bounds__(256) void gemm_qkv(
    const __half* __restrict__ x,
    const __half* __restrict__ Wq, const __half* __restrict__ Wk, const __half* __restrict__ Wv,
    float* __restrict__ Cq, float* __restrict__ Ck, float* __restrict__ Cv, int K) {
    const int ng = blockIdx.x * BN;
    const __half* W; float* C; int N, n0;
    if (ng < 1024)      { W = Wq; C = Cq; N = 1024; n0 = ng; }
    else if (ng < 1280) { W = Wk; C = Ck; N = 256;  n0 = ng - 1024; }
    else                { W = Wv; C = Cv; N = 256;  n0 = ng - 1280; }
    gemm_core(x, W, C, N, K, blockIdx.y * BM, n0);
}

// ---------------- rope + rmsnorm for Q (writes fp16, pre-scaled by 1/8) ----------------
__global__ void rope_rms_kernel(const float* __restrict__ raw,
                                const float* __restrict__ cosb,
                                const float* __restrict__ sinb,
                                __half* __restrict__ dst, int T) {
    const int warp = threadIdx.x >> 5, lane = threadIdx.x & 31;
    const int t = blockIdx.x * 8 + warp;
    const int h = blockIdx.y, b = blockIdx.z;
    const int NH = gridDim.y;
    const float* src = raw + (((size_t)b * T + t) * NH + h) * 64;
    float x1 = src[lane], x2 = src[32 + lane];
    float c = cosb[(size_t)t * 32 + lane];
    float s = sinb[(size_t)t * 32 + lane];
    float r1 = x1 * c + x2 * s;
    float r2 = x2 * c - x1 * s;
    float ss = r1 * r1 + r2 * r2;
#pragma unroll
    for (int o = 16; o; o >>= 1) ss += __shfl_xor_sync(0xffffffffu, ss, o);
    float inv = rsqrtf(ss * (1.f / 64.f) + 1.1920929e-07f) * 0.125f;  // fold 1/sqrt(D) scale
    __half* d = dst + (((size_t)b * NH + h) * T + t) * 64;
    d[lane] = __float2half(r1 * inv);
    d[32 + lane] = __float2half(r2 * inv);
}

// ---------------- fused K rope+rms AND V gate (writes fp16) ----------------
__global__ void kv_post_kernel(const float* __restrict__ kraw,
                               const float* __restrict__ vraw,
                               const float* __restrict__ x,
                               const float* __restrict__ ve,
                               const float* __restrict__ cosb,
                               const float* __restrict__ sinb,
                               const float* __restrict__ Wgate,
                               __half* __restrict__ k_t,
                               __half* __restrict__ v_t, int T) {
    const int warp = threadIdx.x >> 5, lane = threadIdx.x & 31;
    const int t = blockIdx.x * 8 + warp;
    const int h = blockIdx.y, b = blockIdx.z;
    const size_t tok = (size_t)b * T + t;
    {
        const float* src = kraw + (tok * HKV + h) * 64;
        float x1 = src[lane], x2 = src[32 + lane];
        float c = cosb[(size_t)t * 32 + lane];
        float s = sinb[(size_t)t * 32 + lane];
        float r1 = x1 * c + x2 * s;
        float r2 = x2 * c - x1 * s;
        float ss = r1 * r1 + r2 * r2;
#pragma unroll
        for (int o = 16; o; o >>= 1) ss += __shfl_xor_sync(0xffffffffu, ss, o);
        float inv = rsqrtf(ss * (1.f / 64.f) + 1.1920929e-07f);
        __half* d = k_t + (((size_t)b * HKV + h) * T + t) * 64;
        d[lane] = __float2half(r1 * inv);
        d[32 + lane] = __float2half(r2 * inv);
    }
    {
        float g = x[tok * Ecfg + lane] * Wgate[h * 32 + lane];
#pragma unroll
        for (int o = 16; o; o >>= 1) g += __shfl_xor_sync(0xffffffffu, g, o);
        float gate = 2.f / (1.f + __expf(-g));
        const float* vs = vraw + (tok * HKV + h) * 64;
        const float* ves = ve + (tok * HKV + h) * 64;
        __half* d = v_t + (((size_t)b * HKV + h) * T + t) * 64;
        d[lane] = __float2half(vs[lane] + gate * ves[lane]);
        d[32 + lane] = __float2half(vs[32 + lane] + gate * ves[32 + lane]);
    }
}

// ================ sliding-window flash attention (FP16 wmma) ================
// 128 thr = 4 warps; warp w owns query rows [32w, 32w+32) of a 128-row Q tile.
// K/V (fp16) double-buffered via cp.async. Fixed-max softmax p = exp(s-8),
// valid since q (pre-scaled 1/8) and k are rmsnorm'd -> s <= 8.
__global__ __launch_bounds__(128, 2) void attn_tc(
    const __half* __restrict__ q, const __half* __restrict__ k,
    const __half* __restrict__ v, __half* __restrict__ out,
    const int* __restrict__ wptr, int T) {
    extern __shared__ char smraw[];
    __half* Ks = (__half*)smraw;                           // 2 * 64 * LDK halves
    __half* Vs = Ks + 2 * 64 * LDK;                        // 2 * 64 * LDK halves
    __half* Ps = Vs + 2 * 64 * LDK;                        // 128 * LDK halves
    float*  Ss = (float*)(Ps + 128 * LDK);                 // 128 * LDS_F floats

    const int qtile = blockIdx.x, h = blockIdx.y, b = blockIdx.z;
    const int W = wptr[0];
    const int tid = threadIdx.x;
    const int warp = tid >> 5, lane = tid & 31;
    const int qbase = qtile * 128;
    const int half = lane & 1;

    // persistent Q fragments: 2 strips x 4 k-frags (K=64, k16 per frag)
    wmma::fragment<wmma::matrix_a, 16, 16, 16, __half, wmma::row_major> qf[2][4];
#pragma unroll
    for (int i = 0; i < 2; i++) {
        const __half* qptr = q + ((size_t)(b * Hh + h) * T + qbase + warp * 32 + i * 16) * Dd;
#pragma unroll
        for (int kk = 0; kk < 4; kk++)
            wmma::load_matrix_sync(qf[i][kk], qptr + kk * 16, Dd);
    }
    wmma::fragment<wmma::accumulator, 16, 16, 16, float> oa[2][4];
#pragma unroll
    for (int i = 0; i < 2; i++)
#pragma unroll
        for (int j = 0; j < 4; j++) wmma::fill_fragment(oa[i][j], 0.f);

    const int hkv = h >> 2;
    const __half* kb = k + (size_t)(b * HKV + hkv) * T * Dd;
    const __half* vb = v + (size_t)(b * HKV + hkv) * T * Dd;
    int kmin = qbase - W; if (kmin < 0) kmin = 0;
    const int t0 = kmin >> 6;
    const int ktend = 2 * qtile + 1;

#define LOAD_KV(kt, buf)                                                        \
    {                                                                           \
        const __half* kp = kb + (size_t)(kt) * 64 * Dd;                         \
        const __half* vp = vb + (size_t)(kt) * 64 * Dd;                         \
        __half* kd = Ks + (buf) * 64 * LDK;                                     \
        __half* vd = Vs + (buf) * 64 * LDK;                                     \
        _Pragma("unroll")                                                       \
        for (int i = 0; i < 4; i++) {                                           \
            int ch = tid + i * 128;           /* 0..511 */                      \
            int r = ch >> 3, c8 = (ch & 7) << 3;                                \
            cp16(kd + r * LDK + c8, kp + r * 64 + c8);                          \
            cp16(vd + r * LDK + c8, vp + r * 64 + c8);                          \
        }                                                                       \
    }

    LOAD_KV(t0, 0); CP_COMMIT();
    float l_run[2] = {0.f, 0.f};

    for (int kt = t0; kt <= ktend; ++kt) {
        const int buf = (kt - t0) & 1;
        if (kt < ktend) { LOAD_KV(kt + 1, buf ^ 1); CP_COMMIT(); CP_WAIT1(); }
        else CP_WAIT0();
        __syncthreads();
        const __half* ks = Ks + buf * 64 * LDK;
        const __half* vs = Vs + buf * 64 * LDK;

        // S = Q @ K^T : 32x64 per warp, K-frag shared across the 2 row strips
        {
            wmma::fragment<wmma::accumulator, 16, 16, 16, float> sa[2][4];
#pragma unroll
            for (int i = 0; i < 2; i++)
#pragma unroll
                for (int j = 0; j < 4; j++) wmma::fill_fragment(sa[i][j], 0.f);
#pragma unroll
            for (int kk = 0; kk < 4; kk++) {
#pragma unroll
                for (int j = 0; j < 4; j++) {
                    wmma::fragment<wmma::matrix_b, 16, 16, 16, __half, wmma::col_major> bf;
                    wmma::load_matrix_sync(bf, &ks[(j * 16) * LDK + kk * 16], LDK);
                    wmma::mma_sync(sa[0][j], qf[0][kk], bf, sa[0][j]);
                    wmma::mma_sync(sa[1][j], qf[1][kk], bf, sa[1][j]);
                }
            }
#pragma unroll
            for (int i = 0; i < 2; i++)
#pragma unroll
                for (int j = 0; j < 4; j++)
                    wmma::store_matrix_sync(&Ss[(warp * 32 + i * 16) * LDS_F + j * 16],
                                            sa[i][j], LDS_F, wmma::mem_row_major);
        }
        __syncwarp();

        // fixed-max softmax (fp32), write P as fp16 to Ps
        {
#pragma unroll
            for (int p = 0; p < 2; p++) {
                const int sRow = warp * 32 + p * 16 + (lane >> 1);
                const int qrow = qbase + sRow;
                const float* srow = &Ss[sRow * LDS_F + half * 32];
                __half* prow = &Ps[sRow * LDK + half * 32];
                const int colbase = (kt << 6) + (half << 5);
                const int cmax = qrow - colbase;
                const int cmin = qrow - W - colbase;
                float lacc[4] = {0.f, 0.f, 0.f, 0.f};
#pragma unroll
                for (int c = 0; c < 32; c++) {
                    float pv = 0.f;
                    if (c <= cmax && c >= cmin) {
                        pv = fast_exp2(fmaf(srow[c], LOG2E_F, NBIAS_F));
                        lacc[c & 3] += pv;
                    }
                    prow[c] = __float2half(pv);
                }
                l_run[p] += (lacc[0] + lacc[1]) + (lacc[2] + lacc[3]);
            }
        }
        __syncwarp();

        // O += P @ V : V-frag shared across the 2 row strips
#pragma unroll
        for (int kk = 0; kk < 4; kk++) {
            wmma::fragment<wmma::matrix_a, 16, 16, 16, __half, wmma::row_major> pf[2];
#pragma unroll
            for (int i = 0; i < 2; i++)
                wmma::load_matrix_sync(pf[i], &Ps[(warp * 32 + i * 16) * LDK + kk * 16], LDK);
#pragma unroll
            for (int j = 0; j < 4; j++) {
                wmma::fragment<wmma::matrix_b, 16, 16, 16, __half, wmma::row_major> bf;
                wmma::load_matrix_sync(bf, &vs[(kk * 16) * LDK + j * 16], LDK);
                wmma::mma_sync(oa[0][j], pf[0], bf, oa[0][j]);
                wmma::mma_sync(oa[1][j], pf[1], bf, oa[1][j]);
            }
        }
        __syncthreads();
    }
#undef LOAD_KV

    // epilogue: stage O (fp32), normalize per row, write fp16 y [B,T,H,D]
#pragma unroll
    for (int i = 0; i < 2; i++)
#pragma unroll
        for (int j = 0; j < 4; j++)
            wmma::store_matrix_sync(&Ss[(warp * 32 + i * 16) * LDS_F + j * 16],
                                    oa[i][j], LDS_F, wmma::mem_row_major);
    __syncwarp();
#pragma unroll
    for (int p = 0; p < 2; p++) {
        const int sRow = warp * 32 + p * 16 + (lane >> 1);
        const int qrow = qbase + sRow;
        float l_tot = l_run[p] + __shfl_xor_sync(0xffffffffu, l_run[p], 1);
        float inv = 1.f / l_tot;
        __half* op = out + ((size_t)(b * T + qrow) * Hh + h) * Dd + half * 32;
        const float* orow = &Ss[sRow * LDS_F + half * 32];
#pragma unroll
        for (int c = 0; c < 32; c += 2) {
            __half2 hv = __floats2half2_rn(orow[c] * inv, orow[c + 1] * inv);
            *reinterpret_cast<__half2*>(&op[c]) = hv;
        }
    }
}

// ---------------- launch ----------------
extern "C" void kernel_launch(void* const* d_in, const int* in_sizes, int n_in,
                              void* d_out, int out_size) {
    const float* x     = (const float*)d_in[0];
    const float* ve    = (const float*)d_in[1];
    const float* cosb  = (const float*)d_in[2];
    const float* sinb  = (const float*)d_in[3];
    const float* Wq    = (const float*)d_in[4];
    const float* Wk    = (const float*)d_in[5];
    const float* Wv    = (const float*)d_in[6];
    const float* Wproj = (const float*)d_in[7];
    const float* Wgate = (const float*)d_in[8];
    const int*   wsz   = (const int*)d_in[9];

    int T = in_sizes[2] / 32;
    int B = in_sizes[0] / (T * Ecfg);
    int M = B * T;

    float *qraw, *kraw, *vraw;
    __half *qt, *kt, *vt, *y, *xh, *wqh, *wkh, *wvh, *wph;
    cudaGetSymbolAddress((void**)&qraw, g_qraw);
    cudaGetSymbolAddress((void**)&kraw, g_kraw);
    cudaGetSymbolAddress((void**)&vraw, g_vraw);
    cudaGetSymbolAddress((void**)&qt,   g_qt);
    cudaGetSymbolAddress((void**)&kt,   g_kt);
    cudaGetSymbolAddress((void**)&vt,   g_vt);
    cudaGetSymbolAddress((void**)&y,    g_y);
    cudaGetSymbolAddress((void**)&xh,   g_xh);
    cudaGetSymbolAddress((void**)&wqh,  g_wqh);
    cudaGetSymbolAddress((void**)&wkh,  g_wkh);
    cudaGetSymbolAddress((void**)&wvh,  g_wvh);
    cudaGetSymbolAddress((void**)&wph,  g_wph);

    const int gemm_smem = 2 * (BM + BN) * LDA * 2;                        // 40960
    const int attn_smem = (4 * 64 * LDK + 128 * LDK) * 2 + 128 * LDS_F * 4; // 92160
    cudaFuncSetAttribute(gemm_qkv,  cudaFuncAttributeMaxDynamicSharedMemorySize, gemm_smem);
    cudaFuncSetAttribute(gemm_proj, cudaFuncAttributeMaxDynamicSharedMemorySize, gemm_smem);
    cudaFuncSetAttribute(attn_tc,   cudaFuncAttributeMaxDynamicSharedMemorySize, attn_smem);

    // single fused fp16 convert: x + all 4 weight matrices
    {
        int n4x = M * Ecfg / 4;
        int total = n4x + N4_WQ + N4_WK + N4_WV + N4_WP;
        cvt_all<<<(total + 255) / 256, 256>>>(x, Wq, Wk, Wv, Wproj,
                                              xh, wqh, wkh, wvh, wph, n4x);
    }

    gemm_qkv<<<dim3(1536 / BN, M / BM), 256, gemm_smem>>>(xh, wqh, wkh, wvh, qraw, kraw, vraw, Ecfg);

    rope_rms_kernel<<<dim3(T / 8, Hh, B), 256>>>(qraw, cosb, sinb, qt, T);
    kv_post_kernel <<<dim3(T / 8, HKV, B), 256>>>(kraw, vraw, x, ve, cosb, sinb, Wgate, kt, vt, T);

    attn_tc<<<dim3(T / 128, Hh, B), 128, attn_smem>>>(qt, kt, vt, y, wsz, T);

    gemm_proj<<<dim3(Ecfg / BN, M / BM), 256, gemm_smem>>>(y, wph, (float*)d_out, Ecfg);
}

// round 10
// speedup vs baseline: 3.3784x; 1.4653x over previous
#include <cuda_runtime.h>
#include <cuda_fp16.h>
#include <mma.h>
#include <cstdint>

using namespace nvcuda;

#define Ecfg 1024
#define Hh   16
#define HKV  4
#define Dd   64

#define BM  128
#define BN  128
#define LDA 40    // halves
#define LDK 72    // halves; rows 8-apart land in distinct banks for ldmatrix

// ---------------- scratch (device globals) ----------------
__device__ float  g_qraw[2 * 2048 * 1024];
__device__ float  g_kraw[2 * 2048 * 256];
__device__ float  g_vraw[2 * 2048 * 256];
__device__ __half g_qt [2 * 16 * 2048 * 64];
__device__ __half g_kt [2 * 4  * 2048 * 64];
__device__ __half g_vt [2 * 4  * 2048 * 64];
__device__ __half g_y  [2 * 2048 * 1024];
__device__ __half g_xh [2 * 2048 * 1024];
__device__ __half g_wqh[1024 * 1024];
__device__ __half g_wkh[256 * 1024];
__device__ __half g_wvh[256 * 1024];
__device__ __half g_wph[1024 * 1024];

// ---------------- cp.async helpers ----------------
__device__ __forceinline__ void cp16(void* smem_dst, const void* gsrc) {
    uint32_t s = (uint32_t)__cvta_generic_to_shared(smem_dst);
    asm volatile("cp.async.cg.shared.global [%0], [%1], 16;\n" :: "r"(s), "l"(gsrc));
}
#define CP_COMMIT() asm volatile("cp.async.commit_group;\n" ::: "memory")
#define CP_WAIT1()  asm volatile("cp.async.wait_group 1;\n" ::: "memory")
#define CP_WAIT0()  asm volatile("cp.async.wait_group 0;\n" ::: "memory")

__device__ __forceinline__ uint32_t smem_u32(const void* p) {
    return (uint32_t)__cvta_generic_to_shared(p);
}

// ---------------- mma / ldmatrix primitives ----------------
__device__ __forceinline__ void mma16816(float d[4], const uint32_t a[4],
                                         uint32_t b0, uint32_t b1) {
    asm volatile(
        "mma.sync.aligned.m16n8k16.row.col.f32.f16.f16.f32 "
        "{%0,%1,%2,%3}, {%4,%5,%6,%7}, {%8,%9}, {%0,%1,%2,%3};"
        : "+f"(d[0]), "+f"(d[1]), "+f"(d[2]), "+f"(d[3])
        : "r"(a[0]), "r"(a[1]), "r"(a[2]), "r"(a[3]), "r"(b0), "r"(b1));
}
__device__ __forceinline__ void ldm4(uint32_t r[4], uint32_t addr) {
    asm volatile("ldmatrix.sync.aligned.m8n8.x4.shared.b16 {%0,%1,%2,%3}, [%4];"
                 : "=r"(r[0]), "=r"(r[1]), "=r"(r[2]), "=r"(r[3]) : "r"(addr));
}
__device__ __forceinline__ void ldm4t(uint32_t r[4], uint32_t addr) {
    asm volatile("ldmatrix.sync.aligned.m8n8.x4.trans.shared.b16 {%0,%1,%2,%3}, [%4];"
                 : "=r"(r[0]), "=r"(r[1]), "=r"(r[2]), "=r"(r[3]) : "r"(addr));
}

// ---------------- fast exp2 (no MUFU) ----------------
__device__ __forceinline__ float fast_exp2(float x) {
    float t = x + 12582912.0f;
    int   ei = __float_as_int(t) - 0x4B400000;
    float f = x - (t - 12582912.0f);
    float e = fmaf(f, 0.0013333558f, 0.0096181291f);
    e = fmaf(f, e, 0.0555041087f);
    e = fmaf(f, e, 0.2402265070f);
    e = fmaf(f, e, 0.6931471806f);
    e = fmaf(f, e, 1.0f);
    return __int_as_float(__float_as_int(e) + (ei << 23));
}
#define LOG2E_F  1.4426950408889634f
#define NBIAS_F  (-11.541560327111707f)   /* -8 * log2e */

// ---------------- fused fp16 convert of x + all weights (1 launch) ----------------
#define N4_WQ 262144
#define N4_WK 65536
#define N4_WV 65536
#define N4_WP 262144
__global__ void cvt_all(const float* __restrict__ x,  const float* __restrict__ wq,
                        const float* __restrict__ wk, const float* __restrict__ wv,
                        const float* __restrict__ wp,
                        __half* __restrict__ xo, __half* __restrict__ wqo,
                        __half* __restrict__ wko, __half* __restrict__ wvo,
                        __half* __restrict__ wpo, int n4x) {
    int i = blockIdx.x * blockDim.x + threadIdx.x;
    const float4* s; __half* d; int j;
    if (i < n4x) { s = (const float4*)x; d = xo; j = i; }
    else {
        i -= n4x;
        if (i < N4_WQ)                          { s = (const float4*)wq; d = wqo; j = i; }
        else if (i < N4_WQ + N4_WK)             { s = (const float4*)wk; d = wko; j = i - N4_WQ; }
        else if (i < N4_WQ + N4_WK + N4_WV)     { s = (const float4*)wv; d = wvo; j = i - N4_WQ - N4_WK; }
        else if (i < N4_WQ + N4_WK + N4_WV + N4_WP) { s = (const float4*)wp; d = wpo; j = i - N4_WQ - N4_WK - N4_WV; }
        else return;
    }
    float4 v = s[j];
    __half2 h0 = __floats2half2_rn(v.x, v.y);
    __half2 h1 = __floats2half2_rn(v.z, v.w);
    *reinterpret_cast<__half2*>(&d[j * 4])     = h0;
    *reinterpret_cast<__half2*>(&d[j * 4 + 2]) = h1;
}

// ================= FP16 GEMM, cp.async 2-stage (unchanged from R9) =================
__device__ __forceinline__ void gemm_core(
    const __half* __restrict__ A, const __half* __restrict__ W,
    float* __restrict__ C, int N, int K, int m0, int n0) {
    extern __shared__ __half smh[];
    __half* As = smh;
    __half* Ws = smh + 2 * BM * LDA;
    const int tid = threadIdx.x;
    const int warp = tid >> 5;
    const int wm = warp >> 2;
    const int wn = warp & 3;

    wmma::fragment<wmma::accumulator, 16, 16, 16, float> acc[4][2];
#pragma unroll
    for (int i = 0; i < 4; i++)
#pragma unroll
        for (int j = 0; j < 2; j++) wmma::fill_fragment(acc[i][j], 0.f);

    const __half* Ab = A + (size_t)m0 * K;
    const __half* Wb = W + (size_t)n0 * K;

#define LOAD_SLAB(it, buf)                                                      \
    {                                                                           \
        const int k0 = (it) << 5;                                               \
        __half* ad = As + (buf) * BM * LDA;                                     \
        __half* wd = Ws + (buf) * BN * LDA;                                     \
        _Pragma("unroll")                                                       \
        for (int i = 0; i < 2; i++) {                                           \
            int ch = tid + i * 256;                                             \
            int r = ch >> 2, c8 = (ch & 3) << 3;                                \
            cp16(ad + r * LDA + c8, Ab + (size_t)r * K + k0 + c8);              \
            cp16(wd + r * LDA + c8, Wb + (size_t)r * K + k0 + c8);              \
        }                                                                       \
    }

    const int nIter = K >> 5;
    LOAD_SLAB(0, 0); CP_COMMIT();
    for (int it = 0; it < nIter; ++it) {
        const int buf = it & 1;
        if (it + 1 < nIter) { LOAD_SLAB(it + 1, buf ^ 1); CP_COMMIT(); CP_WAIT1(); }
        else CP_WAIT0();
        __syncthreads();
        const __half* as = As + buf * BM * LDA;
        const __half* ws = Ws + buf * BN * LDA;
#pragma unroll
        for (int kk = 0; kk < 32; kk += 16) {
            wmma::fragment<wmma::matrix_a, 16, 16, 16, __half, wmma::row_major> a[4];
            wmma::fragment<wmma::matrix_b, 16, 16, 16, __half, wmma::col_major> b[2];
#pragma unroll
            for (int i = 0; i < 4; i++)
                wmma::load_matrix_sync(a[i], &as[(wm * 64 + i * 16) * LDA + kk], LDA);
#pragma unroll
            for (int j = 0; j < 2; j++)
                wmma::load_matrix_sync(b[j], &ws[(wn * 32 + j * 16) * LDA + kk], LDA);
#pragma unroll
            for (int i = 0; i < 4; i++)
#pragma unroll
                for (int j = 0; j < 2; j++)
                    wmma::mma_sync(acc[i][j], a[i], b[j], acc[i][j]);
        }
        __syncthreads();
    }
#undef LOAD_SLAB
#pragma unroll
    for (int i = 0; i < 4; i++)
#pragma unroll
        for (int j = 0; j < 2; j++)
            wmma::store_matrix_sync(&C[(size_t)(m0 + wm * 64 + i * 16) * N + n0 + wn * 32 + j * 16],
                                    acc[i][j], N, wmma::mem_row_major);
}

__global__ __launch_bounds__(256) void gemm_proj(
    const __half* __restrict__ A, const __half* __restrict__ W, float* __restrict__ C, int K) {
    gemm_core(A, W, C, Ecfg, K, blockIdx.y * BM, blockIdx.x * BN);
}

__global__ __launch_bounds__(256) void gemm_qkv(
    const __half* __restrict__ x,
    const __half* __restrict__ Wq, const __half* __restrict__ Wk, const __half* __restrict__ Wv,
    float* __restrict__ Cq, float* __restrict__ Ck, float* __restrict__ Cv, int K) {
    const int ng = blockIdx.x * BN;
    const __half* W; float* C; int N, n0;
    if (ng < 1024)      { W = Wq; C = Cq; N = 1024; n0 = ng; }
    else if (ng < 1280) { W = Wk; C = Ck; N = 256;  n0 = ng - 1024; }
    else                { W = Wv; C = Cv; N = 256;  n0 = ng - 1280; }
    gemm_core(x, W, C, N, K, blockIdx.y * BM, n0);
}

// ---------------- rope + rmsnorm for Q (fp16, pre-scaled 1/8) ----------------
__global__ void rope_rms_kernel(const float* __restrict__ raw,
                                const float* __restrict__ cosb,
                                const float* __restrict__ sinb,
                                __half* __restrict__ dst, int T) {
    const int warp = threadIdx.x >> 5, lane = threadIdx.x & 31;
    const int t = blockIdx.x * 8 + warp;
    const int h = blockIdx.y, b = blockIdx.z;
    const int NH = gridDim.y;
    const float* src = raw + (((size_t)b * T + t) * NH + h) * 64;
    float x1 = src[lane], x2 = src[32 + lane];
    float c = cosb[(size_t)t * 32 + lane];
    float s = sinb[(size_t)t * 32 + lane];
    float r1 = x1 * c + x2 * s;
    float r2 = x2 * c - x1 * s;
    float ss = r1 * r1 + r2 * r2;
#pragma unroll
    for (int o = 16; o; o >>= 1) ss += __shfl_xor_sync(0xffffffffu, ss, o);
    float inv = rsqrtf(ss * (1.f / 64.f) + 1.1920929e-07f) * 0.125f;
    __half* d = dst + (((size_t)b * NH + h) * T + t) * 64;
    d[lane] = __float2half(r1 * inv);
    d[32 + lane] = __float2half(r2 * inv);
}

// ---------------- fused K rope+rms AND V gate (fp16) ----------------
__global__ void kv_post_kernel(const float* __restrict__ kraw,
                               const float* __restrict__ vraw,
                               const float* __restrict__ x,
                               const float* __restrict__ ve,
                               const float* __restrict__ cosb,
                               const float* __restrict__ sinb,
                               const float* __restrict__ Wgate,
                               __half* __restrict__ k_t,
                               __half* __restrict__ v_t, int T) {
    const int warp = threadIdx.x >> 5, lane = threadIdx.x & 31;
    const int t = blockIdx.x * 8 + warp;
    const int h = blockIdx.y, b = blockIdx.z;
    const size_t tok = (size_t)b * T + t;
    {
        const float* src = kraw + (tok * HKV + h) * 64;
        float x1 = src[lane], x2 = src[32 + lane];
        float c = cosb[(size_t)t * 32 + lane];
        float s = sinb[(size_t)t * 32 + lane];
        float r1 = x1 * c + x2 * s;
        float r2 = x2 * c - x1 * s;
        float ss = r1 * r1 + r2 * r2;
#pragma unroll
        for (int o = 16; o; o >>= 1) ss += __shfl_xor_sync(0xffffffffu, ss, o);
        float inv = rsqrtf(ss * (1.f / 64.f) + 1.1920929e-07f);
        __half* d = k_t + (((size_t)b * HKV + h) * T + t) * 64;
        d[lane] = __float2half(r1 * inv);
        d[32 + lane] = __float2half(r2 * inv);
    }
    {
        float g = x[tok * Ecfg + lane] * Wgate[h * 32 + lane];
#pragma unroll
        for (int o = 16; o; o >>= 1) g += __shfl_xor_sync(0xffffffffu, g, o);
        float gate = 2.f / (1.f + __expf(-g));
        const float* vs = vraw + (tok * HKV + h) * 64;
        const float* ves = ve + (tok * HKV + h) * 64;
        __half* d = v_t + (((size_t)b * HKV + h) * T + t) * 64;
        d[lane] = __float2half(vs[lane] + gate * ves[lane]);
        d[32 + lane] = __float2half(vs[32 + lane] + gate * ves[32 + lane]);
    }
}

// ================ flash attention: raw mma.m16n8k16 + register softmax ================
// 128 thr = 4 warps; warp owns rows [32w, 32w+32) of a 128-row Q tile.
// Only K/V live in smem (double-buffered). S accum layout == P A-fragment layout,
// so mask/exp/pack all stay in registers; P never touches smem.
__global__ __launch_bounds__(128) void attn_mma(
    const __half* __restrict__ q, const __half* __restrict__ k,
    const __half* __restrict__ v, __half* __restrict__ out,
    const int* __restrict__ wptr, int T) {
    extern __shared__ __half smh[];
    __half* Ks = smh;                  // 2 * 64 * LDK
    __half* Vs = smh + 2 * 64 * LDK;   // 2 * 64 * LDK
    const uint32_t ks0 = smem_u32(Ks);
    const uint32_t vs0 = smem_u32(Vs);

    const int qtile = blockIdx.x, h = blockIdx.y, b = blockIdx.z;
    const int W = wptr[0];
    const int tid = threadIdx.x;
    const int warp = tid >> 5, lane = tid & 31;
    const int qbase = qtile * 128;
    const int rq = lane >> 2;            // row within 8-row group
    const int qc = (lane & 3) << 1;      // column pair base

    // per-thread ldmatrix source offsets (halves)
    const int krow = ((lane >> 4) << 3) + (lane & 7);        // K x4: row in 16-key chunk
    const int kcol = ((lane >> 3) & 1) << 3;                 // K x4: d offset 0/8
    const int vrow = (((lane >> 3) & 1) << 3) + (lane & 7);  // V x4t: row in 16-key chunk
    const int vcol = (lane >> 4) << 3;                       // V x4t: d offset 0/8

    // ---- persistent Q A-fragments from gmem: qa[i][t][4] (i = 16-row strip, t = k16 of D) ----
    uint32_t qa[2][4][4];
#pragma unroll
    for (int i = 0; i < 2; i++) {
        const __half* q0 = q + ((size_t)(b * Hh + h) * T + qbase + warp * 32 + i * 16 + rq) * Dd;
        const __half* q8 = q0 + 8 * Dd;
#pragma unroll
        for (int t = 0; t < 4; t++) {
            qa[i][t][0] = *reinterpret_cast<const uint32_t*>(q0 + t * 16 + qc);
            qa[i][t][1] = *reinterpret_cast<const uint32_t*>(q8 + t * 16 + qc);
            qa[i][t][2] = *reinterpret_cast<const uint32_t*>(q0 + t * 16 + 8 + qc);
            qa[i][t][3] = *reinterpret_cast<const uint32_t*>(q8 + t * 16 + 8 + qc);
        }
    }

    float o[2][8][4];
#pragma unroll
    for (int i = 0; i < 2; i++)
#pragma unroll
        for (int j = 0; j < 8; j++)
#pragma unroll
            for (int c = 0; c < 4; c++) o[i][j][c] = 0.f;
    float lsum[2][2] = {{0.f, 0.f}, {0.f, 0.f}};

    const int hkv = h >> 2;
    const __half* kb = k + (size_t)(b * HKV + hkv) * T * Dd;
    const __half* vb = v + (size_t)(b * HKV + hkv) * T * Dd;
    int kmin = qbase - W; if (kmin < 0) kmin = 0;
    const int t0 = kmin >> 6;
    const int ktend = 2 * qtile + 1;

#define LOAD_KV(kt, buf)                                                        \
    {                                                                           \
        const __half* kp = kb + (size_t)(kt) * 64 * Dd;                         \
        const __half* vp = vb + (size_t)(kt) * 64 * Dd;                         \
        __half* kd = Ks + (buf) * 64 * LDK;                                     \
        __half* vd = Vs + (buf) * 64 * LDK;                                     \
        _Pragma("unroll")                                                       \
        for (int i = 0; i < 4; i++) {                                           \
            int ch = tid + i * 128;                                             \
            int r = ch >> 3, c8 = (ch & 7) << 3;                                \
            cp16(kd + r * LDK + c8, kp + r * 64 + c8);                          \
            cp16(vd + r * LDK + c8, vp + r * 64 + c8);                          \
        }                                                                       \
    }

    LOAD_KV(t0, 0); CP_COMMIT();

    for (int kt = t0; kt <= ktend; ++kt) {
        const int buf = (kt - t0) & 1;
        if (kt < ktend) { LOAD_KV(kt + 1, buf ^ 1); CP_COMMIT(); CP_WAIT1(); }
        else CP_WAIT0();
        __syncthreads();
        const uint32_t ksb = ks0 + buf * 64 * LDK * 2;
        const uint32_t vsb = vs0 + buf * 64 * LDK * 2;

        // process 16 keys at a time: t = k16 chunk within the 64-key tile
#pragma unroll
        for (int t = 0; t < 4; t++) {
            // ---- S = Q K^T for this 16-key chunk (2 n8 tiles jj=0,1) ----
            float s[2][2][4];
#pragma unroll
            for (int i = 0; i < 2; i++)
#pragma unroll
                for (int jj = 0; jj < 2; jj++)
#pragma unroll
                    for (int c = 0; c < 4; c++) s[i][jj][c] = 0.f;
#pragma unroll
            for (int kd = 0; kd < 4; kd++) {
                uint32_t kbf[4];
                ldm4(kbf, ksb + (uint32_t)(((t * 16 + krow) * LDK + kd * 16 + kcol) * 2));
                mma16816(s[0][0], qa[0][kd], kbf[0], kbf[1]);
                mma16816(s[0][1], qa[0][kd], kbf[2], kbf[3]);
                mma16816(s[1][0], qa[1][kd], kbf[0], kbf[1]);
                mma16816(s[1][1], qa[1][kd], kbf[2], kbf[3]);
            }
            // ---- register softmax: p = exp(s - 8), window mask; pack P A-frags ----
            uint32_t pa[2][4];
#pragma unroll
            for (int i = 0; i < 2; i++) {
                const int row0 = qbase + warp * 32 + i * 16 + rq;
#pragma unroll
                for (int jj = 0; jj < 2; jj++) {
                    const int colb = (kt << 6) + t * 16 + jj * 8 + qc;
#pragma unroll
                    for (int c = 0; c < 4; c++) {
                        const int row = row0 + ((c >> 1) << 3);
                        const int col = colb + (c & 1);
                        float pv = 0.f;
                        if (col <= row && col >= row - W) {
                            pv = fast_exp2(fmaf(s[i][jj][c], LOG2E_F, NBIAS_F));
                            lsum[i][c >> 1] += pv;
                        }
                        s[i][jj][c] = pv;
                    }
                    __half2 lo = __floats2half2_rn(s[i][jj][0], s[i][jj][1]);
                    __half2 hi = __floats2half2_rn(s[i][jj][2], s[i][jj][3]);
                    pa[i][jj * 2 + 0] = *reinterpret_cast<uint32_t*>(&lo);
                    pa[i][jj * 2 + 1] = *reinterpret_cast<uint32_t*>(&hi);
                }
            }
            // ---- O += P V for this 16-key chunk ----
#pragma unroll
            for (int jdp = 0; jdp < 4; jdp++) {
                uint32_t vbf[4];
                ldm4t(vbf, vsb + (uint32_t)(((t * 16 + vrow) * LDK + jdp * 16 + vcol) * 2));
                mma16816(o[0][jdp * 2 + 0], pa[0], vbf[0], vbf[1]);
                mma16816(o[0][jdp * 2 + 1], pa[0], vbf[2], vbf[3]);
                mma16816(o[1][jdp * 2 + 0], pa[1], vbf[0], vbf[1]);
                mma16816(o[1][jdp * 2 + 1], pa[1], vbf[2], vbf[3]);
            }
        }
        __syncthreads();
    }
#undef LOAD_KV

    // ---- epilogue: quad-reduce l, normalize, write fp16 y [B,T,H,D] ----
#pragma unroll
    for (int i = 0; i < 2; i++) {
#pragma unroll
        for (int rh = 0; rh < 2; rh++) {
            float l = lsum[i][rh];
            l += __shfl_xor_sync(0xffffffffu, l, 1);
            l += __shfl_xor_sync(0xffffffffu, l, 2);
            const float inv = 1.f / l;
            const int qrow = qbase + warp * 32 + i * 16 + rq + rh * 8;
            __half* op = out + ((size_t)(b * T + qrow) * Hh + h) * Dd + qc;
#pragma unroll
            for (int jd = 0; jd < 8; jd++) {
                __half2 hv = __floats2half2_rn(o[i][jd][rh * 2] * inv,
                                               o[i][jd][rh * 2 + 1] * inv);
                *reinterpret_cast<__half2*>(op + jd * 8) = hv;
            }
        }
    }
}

// ---------------- launch ----------------
extern "C" void kernel_launch(void* const* d_in, const int* in_sizes, int n_in,
                              void* d_out, int out_size) {
    const float* x     = (const float*)d_in[0];
    const float* ve    = (const float*)d_in[1];
    const float* cosb  = (const float*)d_in[2];
    const float* sinb  = (const float*)d_in[3];
    const float* Wq    = (const float*)d_in[4];
    const float* Wk    = (const float*)d_in[5];
    const float* Wv    = (const float*)d_in[6];
    const float* Wproj = (const float*)d_in[7];
    const float* Wgate = (const float*)d_in[8];
    const int*   wsz   = (const int*)d_in[9];

    int T = in_sizes[2] / 32;
    int B = in_sizes[0] / (T * Ecfg);
    int M = B * T;

    float *qraw, *kraw, *vraw;
    __half *qt, *kt, *vt, *y, *xh, *wqh, *wkh, *wvh, *wph;
    cudaGetSymbolAddress((void**)&qraw, g_qraw);
    cudaGetSymbolAddress((void**)&kraw, g_kraw);
    cudaGetSymbolAddress((void**)&vraw, g_vraw);
    cudaGetSymbolAddress((void**)&qt,   g_qt);
    cudaGetSymbolAddress((void**)&kt,   g_kt);
    cudaGetSymbolAddress((void**)&vt,   g_vt);
    cudaGetSymbolAddress((void**)&y,    g_y);
    cudaGetSymbolAddress((void**)&xh,   g_xh);
    cudaGetSymbolAddress((void**)&wqh,  g_wqh);
    cudaGetSymbolAddress((void**)&wkh,  g_wkh);
    cudaGetSymbolAddress((void**)&wvh,  g_wvh);
    cudaGetSymbolAddress((void**)&wph,  g_wph);

    const int gemm_smem = 2 * (BM + BN) * LDA * 2;   // 40960
    const int attn_smem = 4 * 64 * LDK * 2;          // 36864
    cudaFuncSetAttribute(gemm_qkv,  cudaFuncAttributeMaxDynamicSharedMemorySize, gemm_smem);
    cudaFuncSetAttribute(gemm_proj, cudaFuncAttributeMaxDynamicSharedMemorySize, gemm_smem);
    cudaFuncSetAttribute(attn_mma,  cudaFuncAttributeMaxDynamicSharedMemorySize, attn_smem);

    {
        int n4x = M * Ecfg / 4;
        int total = n4x + N4_WQ + N4_WK + N4_WV + N4_WP;
        cvt_all<<<(total + 255) / 256, 256>>>(x, Wq, Wk, Wv, Wproj,
                                              xh, wqh, wkh, wvh, wph, n4x);
    }

    gemm_qkv<<<dim3(1536 / BN, M / BM), 256, gemm_smem>>>(xh, wqh, wkh, wvh, qraw, kraw, vraw, Ecfg);

    rope_rms_kernel<<<dim3(T / 8, Hh, B), 256>>>(qraw, cosb, sinb, qt, T);
    kv_post_kernel <<<dim3(T / 8, HKV, B), 256>>>(kraw, vraw, x, ve, cosb, sinb, Wgate, kt, vt, T);

    attn_mma<<<dim3(T / 128, Hh, B), 128, attn_smem>>>(qt, kt, vt, y, wsz, T);

    gemm_proj<<<dim3(Ecfg / BN, M / BM), 256, gemm_smem>>>(y, wph, (float*)d_out, Ecfg);
}